// round 1
// baseline (speedup 1.0000x reference)
#include <cuda_runtime.h>
#include <cstdint>
#include <cstddef>

#define DM 1024
#define NH 16
#define DK 64
#define BB 2
#define SSEQ 2048
#define MTOT (BB*SSEQ)     // 4096
#define BH (BB*NH)         // 32

// Scratch (allocation-free rule: __device__ globals)
__device__ float g_q[(size_t)BH*SSEQ*DK];      // [B,H,S,dk]
__device__ float g_k[(size_t)BH*SSEQ*DK];
__device__ float g_v[(size_t)BH*SSEQ*DK];
__device__ float g_attn[(size_t)MTOT*DM];      // merged [B,S,D]

// ---------------------------------------------------------------------------
// C = A[M,1024] @ W[1024,1024]^T + bias. If split!=0, scatter into [B,H,S,dk].
// 64x64 tile, BK=16, 256 threads, 4x4 micro-tile.
// ---------------------------------------------------------------------------
__global__ void gemm_proj(const float* __restrict__ A, const float* __restrict__ W,
                          const float* __restrict__ bias, float* __restrict__ out,
                          int split)
{
    __shared__ float As[16][65];
    __shared__ float Ws[16][65];
    const int tx = threadIdx.x, ty = threadIdx.y;
    const int tid = ty * 16 + tx;
    const int m0 = blockIdx.y * 64;
    const int n0 = blockIdx.x * 64;

    float acc[4][4] = {};

    const int kl = tid & 15;     // k within tile
    const int rl = tid >> 4;     // 0..15 row base

    for (int k0 = 0; k0 < 1024; k0 += 16) {
#pragma unroll
        for (int p = 0; p < 4; p++) {
            As[kl][rl + p * 16] = A[(size_t)(m0 + rl + p * 16) * 1024 + k0 + kl];
            Ws[kl][rl + p * 16] = W[(size_t)(n0 + rl + p * 16) * 1024 + k0 + kl];
        }
        __syncthreads();
#pragma unroll
        for (int kk = 0; kk < 16; kk++) {
            float a[4], b[4];
#pragma unroll
            for (int i = 0; i < 4; i++) a[i] = As[kk][ty * 4 + i];
#pragma unroll
            for (int j = 0; j < 4; j++) b[j] = Ws[kk][tx * 4 + j];
#pragma unroll
            for (int i = 0; i < 4; i++)
#pragma unroll
                for (int j = 0; j < 4; j++)
                    acc[i][j] += a[i] * b[j];
        }
        __syncthreads();
    }

#pragma unroll
    for (int i = 0; i < 4; i++) {
        const int m = m0 + ty * 4 + i;
        const int b_ = m / SSEQ, s = m % SSEQ;
#pragma unroll
        for (int j = 0; j < 4; j++) {
            const int n = n0 + tx * 4 + j;
            const float v = acc[i][j] + bias[n];
            if (split) {
                const int h = n >> 6, d = n & 63;
                out[(((size_t)(b_ * NH + h) * SSEQ + s) << 6) + d] = v;
            } else {
                out[(size_t)m * DM + n] = v;
            }
        }
    }
}

// ---------------------------------------------------------------------------
// scores[bh,i,j] = scale * dot(q[bh,i,:], k[bh,j,:]), masked.
// One block computes a 64x64 tile; K-dim = 64 fits entirely in smem.
// ---------------------------------------------------------------------------
__global__ void scores_kernel(const unsigned char* __restrict__ mask,
                              float* __restrict__ scores)
{
    __shared__ float Qs[64][65];
    __shared__ float Ks[64][65];
    const int tx = threadIdx.x, ty = threadIdx.y;
    const int tid = ty * 16 + tx;
    const int bh = blockIdx.z;
    const int i0 = blockIdx.y * 64, j0 = blockIdx.x * 64;

    const float* q = g_q + (size_t)bh * SSEQ * DK;
    const float* k = g_k + (size_t)bh * SSEQ * DK;

    {
        const int d = tid & 63;
        const int r = tid >> 6;   // 0..3
#pragma unroll
        for (int p = 0; p < 16; p++) {
            Qs[d][r + p * 4] = q[(size_t)(i0 + r + p * 4) * DK + d];
            Ks[d][r + p * 4] = k[(size_t)(j0 + r + p * 4) * DK + d];
        }
    }
    __syncthreads();

    float acc[4][4] = {};
#pragma unroll
    for (int dd = 0; dd < 64; dd++) {
        float a[4], b[4];
#pragma unroll
        for (int i = 0; i < 4; i++) a[i] = Qs[dd][ty * 4 + i];
#pragma unroll
        for (int j = 0; j < 4; j++) b[j] = Ks[dd][tx * 4 + j];
#pragma unroll
        for (int i = 0; i < 4; i++)
#pragma unroll
            for (int j = 0; j < 4; j++)
                acc[i][j] += a[i] * b[j];
    }

    const float scale = 0.125f;  // 1/sqrt(64)
    const int b_ = bh / NH;
#pragma unroll
    for (int i = 0; i < 4; i++) {
        const int ig = i0 + ty * 4 + i;
#pragma unroll
        for (int j = 0; j < 4; j++) {
            const int jg = j0 + tx * 4 + j;
            float v = acc[i][j] * scale;
            if (mask[(size_t)(b_ * SSEQ + ig) * SSEQ + jg]) v = -1e9f;
            scores[((size_t)bh * SSEQ + ig) * SSEQ + jg] = v;
        }
    }
}

// ---------------------------------------------------------------------------
// In-place row softmax over 2048 elements. One block (256 thr) per row.
// ---------------------------------------------------------------------------
__global__ void softmax_kernel(float* __restrict__ p)
{
    __shared__ float red[256];
    const int t = threadIdx.x;
    float* pr = p + (size_t)blockIdx.x * SSEQ;

    float x[8];
    float mx = -1e30f;
#pragma unroll
    for (int i = 0; i < 8; i++) { x[i] = pr[t + i * 256]; mx = fmaxf(mx, x[i]); }
    red[t] = mx;
    __syncthreads();
    for (int s = 128; s > 0; s >>= 1) {
        if (t < s) red[t] = fmaxf(red[t], red[t + s]);
        __syncthreads();
    }
    mx = red[0];
    __syncthreads();

    float sum = 0.f;
#pragma unroll
    for (int i = 0; i < 8; i++) { x[i] = __expf(x[i] - mx); sum += x[i]; }
    red[t] = sum;
    __syncthreads();
    for (int s = 128; s > 0; s >>= 1) {
        if (t < s) red[t] += red[t + s];
        __syncthreads();
    }
    const float inv = 1.0f / red[0];
#pragma unroll
    for (int i = 0; i < 8; i++) pr[t + i * 256] = x[i] * inv;
}

// ---------------------------------------------------------------------------
// attn[bh,i,:] = P[bh,i,:] @ v[bh,:,:]   (M=2048, N=64, K=2048)
// Writes merged [B,S,H*dk] layout for the final projection.
// ---------------------------------------------------------------------------
__global__ void pv_kernel(const float* __restrict__ p)
{
    __shared__ float Ps[32][65];
    __shared__ float Vs[32][65];
    const int tx = threadIdx.x, ty = threadIdx.y;
    const int tid = ty * 16 + tx;
    const int bh = blockIdx.y;
    const int i0 = blockIdx.x * 64;

    const float* P = p + (size_t)bh * SSEQ * SSEQ;
    const float* v = g_v + (size_t)bh * SSEQ * DK;

    float acc[4][4] = {};
    const int klP = tid & 31, rlP = tid >> 5;  // P: 8 rows/pass
    const int dlV = tid & 63, jlV = tid >> 6;  // V: 4 rows/pass

    for (int k0 = 0; k0 < SSEQ; k0 += 32) {
#pragma unroll
        for (int pp = 0; pp < 8; pp++)
            Ps[klP][rlP + pp * 8] = P[(size_t)(i0 + rlP + pp * 8) * SSEQ + k0 + klP];
#pragma unroll
        for (int pp = 0; pp < 8; pp++)
            Vs[jlV + pp * 4][dlV] = v[(size_t)(k0 + jlV + pp * 4) * DK + dlV];
        __syncthreads();
#pragma unroll
        for (int kk = 0; kk < 32; kk++) {
            float a[4], b[4];
#pragma unroll
            for (int i = 0; i < 4; i++) a[i] = Ps[kk][ty * 4 + i];
#pragma unroll
            for (int j = 0; j < 4; j++) b[j] = Vs[kk][tx * 4 + j];
#pragma unroll
            for (int i = 0; i < 4; i++)
#pragma unroll
                for (int j = 0; j < 4; j++)
                    acc[i][j] += a[i] * b[j];
        }
        __syncthreads();
    }

    const int b_ = bh / NH, h = bh % NH;
#pragma unroll
    for (int i = 0; i < 4; i++) {
        const int s = i0 + ty * 4 + i;
#pragma unroll
        for (int j = 0; j < 4; j++) {
            const int d = tx * 4 + j;
            g_attn[(size_t)(b_ * SSEQ + s) * DM + h * DK + d] = acc[i][j];
        }
    }
}

// ---------------------------------------------------------------------------
extern "C" void kernel_launch(void* const* d_in, const int* in_sizes, int n_in,
                              void* d_out, int out_size)
{
    const float* Q   = (const float*)d_in[0];
    const float* K   = (const float*)d_in[1];
    const float* V   = (const float*)d_in[2];
    const unsigned char* mask = (const unsigned char*)d_in[3];
    const float* WQw = (const float*)d_in[4];
    const float* WQb = (const float*)d_in[5];
    const float* WKw = (const float*)d_in[6];
    const float* WKb = (const float*)d_in[7];
    const float* WVw = (const float*)d_in[8];
    const float* WVb = (const float*)d_in[9];
    const float* Wow = (const float*)d_in[10];
    const float* Wob = (const float*)d_in[11];

    float* out   = (float*)d_out;                       // [B,S,D] outputs
    float* attnw = out + (size_t)MTOT * DM;             // [B,H,S,S] attn weights

    float *pq, *pk, *pv, *pa;
    cudaGetSymbolAddress((void**)&pq, g_q);
    cudaGetSymbolAddress((void**)&pk, g_k);
    cudaGetSymbolAddress((void**)&pv, g_v);
    cudaGetSymbolAddress((void**)&pa, g_attn);

    dim3 blk(16, 16);

    // Projections (with fused split-heads scatter)
    gemm_proj<<<dim3(16, 64), blk>>>(Q, WQw, WQb, pq, 1);
    gemm_proj<<<dim3(16, 64), blk>>>(K, WKw, WKb, pk, 1);
    gemm_proj<<<dim3(16, 64), blk>>>(V, WVw, WVb, pv, 1);

    // Scores -> d_out attn region, softmax in place
    scores_kernel<<<dim3(32, 32, 32), blk>>>(mask, attnw);
    softmax_kernel<<<BH * SSEQ, 256>>>(attnw);

    // P @ V -> merged attn
    pv_kernel<<<dim3(32, 32), blk>>>(attnw);

    // Output projection
    gemm_proj<<<dim3(16, 64), blk>>>(pa, Wow, Wob, out, 0);
}

// round 2
// speedup vs baseline: 2.3389x; 2.3389x over previous
#include <cuda_runtime.h>
#include <cstdint>
#include <cstddef>

#define DM 1024
#define NH 16
#define DK 64
#define BB 2
#define SSEQ 2048
#define MTOT (BB*SSEQ)     // 4096
#define BH (BB*NH)         // 32

// Scratch (allocation-free rule: __device__ globals)
__device__ float g_q[(size_t)BH*SSEQ*DK];      // [B,H,S,dk]
__device__ float g_k[(size_t)BH*SSEQ*DK];      // [B,H,S,dk]
__device__ float g_vT[(size_t)BH*DK*SSEQ];     // [B,H,dk,S]  (transposed V)
__device__ float g_attn[(size_t)MTOT*DM];      // merged [B,S,D]

// ---------------------------------------------------------------------------
// TF32 mma.sync helpers
// ---------------------------------------------------------------------------
__device__ __forceinline__ uint32_t f2tf32(float x) {
    uint32_t r;
    asm("cvt.rna.tf32.f32 %0, %1;\n" : "=r"(r) : "f"(x));
    return r;
}
__device__ __forceinline__ uint4 cvt4(float4 v) {
    uint4 r;
    r.x = f2tf32(v.x); r.y = f2tf32(v.y); r.z = f2tf32(v.z); r.w = f2tf32(v.w);
    return r;
}
__device__ __forceinline__ void mma_tf32(float* c, const uint32_t* a, const uint32_t* b) {
    asm volatile(
        "mma.sync.aligned.m16n8k8.row.col.f32.tf32.tf32.f32 "
        "{%0,%1,%2,%3}, {%4,%5,%6,%7}, {%8,%9}, {%0,%1,%2,%3};\n"
        : "+f"(c[0]), "+f"(c[1]), "+f"(c[2]), "+f"(c[3])
        : "r"(a[0]), "r"(a[1]), "r"(a[2]), "r"(a[3]), "r"(b[0]), "r"(b[1]));
}

// ---------------------------------------------------------------------------
// Projection GEMM: C[4096,1024] = A[4096,1024] @ W[1024,1024]^T + bias
// 128x128 tile, BK=16, 256 thr (8 warps: 4m x 2n; warp tile 32x64).
// mode 0: plain out[m][n]; mode 1: split-heads [bh,s,64]; mode 2: V^T [bh,64,s]
// ---------------------------------------------------------------------------
__global__ void __launch_bounds__(256) proj_tf32(
    const float* __restrict__ A, const float* __restrict__ W,
    const float* __restrict__ bias, float* __restrict__ out, int mode)
{
    __shared__ uint32_t As[128][20];
    __shared__ uint32_t Bs[128][20];
    const int tid = threadIdx.x;
    const int m0 = blockIdx.y * 128, n0 = blockIdx.x * 128;
    const int lane = tid & 31, warp = tid >> 5;
    const int wm = (warp & 3) * 32, wn = (warp >> 2) * 64;
    const int g = lane >> 2, t = lane & 3;
    const int lr = tid >> 2;            // 0..63
    const int lk = (tid & 3) * 4;       // 0,4,8,12

    const float* Ab = A + (size_t)(m0 + lr) * 1024 + lk;
    const float* Wb = W + (size_t)(n0 + lr) * 1024 + lk;

    float4 ra0 = *(const float4*)(Ab);
    float4 ra1 = *(const float4*)(Ab + (size_t)64 * 1024);
    float4 rb0 = *(const float4*)(Wb);
    float4 rb1 = *(const float4*)(Wb + (size_t)64 * 1024);

    float c[2][8][4] = {};

    for (int k0 = 16; k0 <= 1024; k0 += 16) {
        *(uint4*)&As[lr][lk]      = cvt4(ra0);
        *(uint4*)&As[lr + 64][lk] = cvt4(ra1);
        *(uint4*)&Bs[lr][lk]      = cvt4(rb0);
        *(uint4*)&Bs[lr + 64][lk] = cvt4(rb1);
        __syncthreads();
        if (k0 < 1024) {
            ra0 = *(const float4*)(Ab + k0);
            ra1 = *(const float4*)(Ab + (size_t)64 * 1024 + k0);
            rb0 = *(const float4*)(Wb + k0);
            rb1 = *(const float4*)(Wb + (size_t)64 * 1024 + k0);
        }
#pragma unroll
        for (int ks = 0; ks < 2; ks++) {
            const int kb = ks * 8;
            uint32_t af[2][4], bf[8][2];
#pragma unroll
            for (int mi = 0; mi < 2; mi++) {
                const int r = wm + mi * 16 + g;
                af[mi][0] = As[r][kb + t];
                af[mi][1] = As[r + 8][kb + t];
                af[mi][2] = As[r][kb + t + 4];
                af[mi][3] = As[r + 8][kb + t + 4];
            }
#pragma unroll
            for (int ni = 0; ni < 8; ni++) {
                const int cc = wn + ni * 8 + g;
                bf[ni][0] = Bs[cc][kb + t];
                bf[ni][1] = Bs[cc][kb + t + 4];
            }
#pragma unroll
            for (int mi = 0; mi < 2; mi++)
#pragma unroll
                for (int ni = 0; ni < 8; ni++)
                    mma_tf32(c[mi][ni], af[mi], bf[ni]);
        }
        __syncthreads();
    }

#pragma unroll
    for (int mi = 0; mi < 2; mi++) {
#pragma unroll
        for (int rr = 0; rr < 2; rr++) {
            const int m = m0 + wm + mi * 16 + g + rr * 8;
            const int b_ = m >> 11, s = m & 2047;
#pragma unroll
            for (int ni = 0; ni < 8; ni++) {
                const int n = n0 + wn + ni * 8 + 2 * t;
                const float v0 = c[mi][ni][rr * 2 + 0] + bias[n];
                const float v1 = c[mi][ni][rr * 2 + 1] + bias[n + 1];
                if (mode == 0) {
                    *(float2*)&out[(size_t)m * 1024 + n] = make_float2(v0, v1);
                } else if (mode == 1) {
                    const int h = n >> 6, d = n & 63;
                    *(float2*)&out[(((size_t)(b_ * 16 + h) * 2048 + s) << 6) + d] = make_float2(v0, v1);
                } else {
                    const int h = n >> 6, d = n & 63;
                    out[((size_t)(b_ * 16 + h) * 64 + d) * 2048 + s] = v0;
                    out[((size_t)(b_ * 16 + h) * 64 + d + 1) * 2048 + s] = v1;
                }
            }
        }
    }
}

// ---------------------------------------------------------------------------
// Scores: P[bh,i,j] = 0.125 * q[bh,i,:]·k[bh,j,:], masked.  K=64.
// ---------------------------------------------------------------------------
__global__ void __launch_bounds__(256) scores_tf32(
    const unsigned char* __restrict__ mask, float* __restrict__ P)
{
    __shared__ uint32_t As[128][20];
    __shared__ uint32_t Bs[128][20];
    const int tid = threadIdx.x;
    const int bh = blockIdx.z;
    const int m0 = blockIdx.y * 128, n0 = blockIdx.x * 128;
    const int lane = tid & 31, warp = tid >> 5;
    const int wm = (warp & 3) * 32, wn = (warp >> 2) * 64;
    const int g = lane >> 2, t = lane & 3;
    const int lr = tid >> 2;
    const int lk = (tid & 3) * 4;

    const float* Ab = g_q + (size_t)bh * SSEQ * 64 + (size_t)(m0 + lr) * 64 + lk;
    const float* Bb = g_k + (size_t)bh * SSEQ * 64 + (size_t)(n0 + lr) * 64 + lk;

    float4 ra0 = *(const float4*)(Ab);
    float4 ra1 = *(const float4*)(Ab + (size_t)64 * 64);
    float4 rb0 = *(const float4*)(Bb);
    float4 rb1 = *(const float4*)(Bb + (size_t)64 * 64);

    float c[2][8][4] = {};

    for (int k0 = 16; k0 <= 64; k0 += 16) {
        *(uint4*)&As[lr][lk]      = cvt4(ra0);
        *(uint4*)&As[lr + 64][lk] = cvt4(ra1);
        *(uint4*)&Bs[lr][lk]      = cvt4(rb0);
        *(uint4*)&Bs[lr + 64][lk] = cvt4(rb1);
        __syncthreads();
        if (k0 < 64) {
            ra0 = *(const float4*)(Ab + k0);
            ra1 = *(const float4*)(Ab + (size_t)64 * 64 + k0);
            rb0 = *(const float4*)(Bb + k0);
            rb1 = *(const float4*)(Bb + (size_t)64 * 64 + k0);
        }
#pragma unroll
        for (int ks = 0; ks < 2; ks++) {
            const int kb = ks * 8;
            uint32_t af[2][4], bf[8][2];
#pragma unroll
            for (int mi = 0; mi < 2; mi++) {
                const int r = wm + mi * 16 + g;
                af[mi][0] = As[r][kb + t];
                af[mi][1] = As[r + 8][kb + t];
                af[mi][2] = As[r][kb + t + 4];
                af[mi][3] = As[r + 8][kb + t + 4];
            }
#pragma unroll
            for (int ni = 0; ni < 8; ni++) {
                const int cc = wn + ni * 8 + g;
                bf[ni][0] = Bs[cc][kb + t];
                bf[ni][1] = Bs[cc][kb + t + 4];
            }
#pragma unroll
            for (int mi = 0; mi < 2; mi++)
#pragma unroll
                for (int ni = 0; ni < 8; ni++)
                    mma_tf32(c[mi][ni], af[mi], bf[ni]);
        }
        __syncthreads();
    }

    const int b_ = bh >> 4;
    float* Pr = P + (size_t)bh * SSEQ * SSEQ;
    const unsigned char* mk = mask + (size_t)b_ * SSEQ * SSEQ;
#pragma unroll
    for (int mi = 0; mi < 2; mi++) {
#pragma unroll
        for (int rr = 0; rr < 2; rr++) {
            const int i = m0 + wm + mi * 16 + g + rr * 8;
#pragma unroll
            for (int ni = 0; ni < 8; ni++) {
                const int j = n0 + wn + ni * 8 + 2 * t;
                float v0 = c[mi][ni][rr * 2 + 0] * 0.125f;
                float v1 = c[mi][ni][rr * 2 + 1] * 0.125f;
                if (mk[(size_t)i * SSEQ + j])     v0 = -1e9f;
                if (mk[(size_t)i * SSEQ + j + 1]) v1 = -1e9f;
                *(float2*)&Pr[(size_t)i * SSEQ + j] = make_float2(v0, v1);
            }
        }
    }
}

// ---------------------------------------------------------------------------
// In-place row softmax over 2048 elems; 256 thr/row, float4, shuffle reduce.
// ---------------------------------------------------------------------------
__global__ void __launch_bounds__(256) softmax_kernel(float* __restrict__ p)
{
    __shared__ float red[8];
    const int t = threadIdx.x;
    const int lane = t & 31, warp = t >> 5;
    float4* pr = (float4*)(p + (size_t)blockIdx.x * SSEQ);

    float4 x0 = pr[t], x1 = pr[t + 256];
    float mx = fmaxf(fmaxf(fmaxf(x0.x, x0.y), fmaxf(x0.z, x0.w)),
                     fmaxf(fmaxf(x1.x, x1.y), fmaxf(x1.z, x1.w)));
#pragma unroll
    for (int s = 16; s > 0; s >>= 1) mx = fmaxf(mx, __shfl_xor_sync(0xffffffffu, mx, s));
    if (lane == 0) red[warp] = mx;
    __syncthreads();
    if (warp == 0) {
        float v = red[lane & 7];
#pragma unroll
        for (int s = 4; s > 0; s >>= 1) v = fmaxf(v, __shfl_xor_sync(0xffffffffu, v, s));
        if (lane < 8) red[lane] = v;
    }
    __syncthreads();
    mx = red[0];

    x0.x = __expf(x0.x - mx); x0.y = __expf(x0.y - mx);
    x0.z = __expf(x0.z - mx); x0.w = __expf(x0.w - mx);
    x1.x = __expf(x1.x - mx); x1.y = __expf(x1.y - mx);
    x1.z = __expf(x1.z - mx); x1.w = __expf(x1.w - mx);
    float sum = x0.x + x0.y + x0.z + x0.w + x1.x + x1.y + x1.z + x1.w;
#pragma unroll
    for (int s = 16; s > 0; s >>= 1) sum += __shfl_xor_sync(0xffffffffu, sum, s);
    if (lane == 0) red[warp] = sum;
    __syncthreads();
    if (warp == 0) {
        float v = red[lane & 7];
#pragma unroll
        for (int s = 4; s > 0; s >>= 1) v += __shfl_xor_sync(0xffffffffu, v, s);
        if (lane < 8) red[lane] = v;
    }
    __syncthreads();
    const float inv = 1.0f / red[0];

    x0.x *= inv; x0.y *= inv; x0.z *= inv; x0.w *= inv;
    x1.x *= inv; x1.y *= inv; x1.z *= inv; x1.w *= inv;
    pr[t] = x0; pr[t + 256] = x1;
}

// ---------------------------------------------------------------------------
// PV: attn[i,d] = sum_k P[bh,i,k] * V[bh,k,d]  using V^T [bh,64,2048].  NT form.
// 128x64 tile, BK=16, 256 thr (8 warps: 4m x 2n; warp tile 32x32).
// Writes merged [B,S,H*64].
// ---------------------------------------------------------------------------
__global__ void __launch_bounds__(256) pv_tf32(const float* __restrict__ P)
{
    __shared__ uint32_t As[128][20];
    __shared__ uint32_t Bs[64][20];
    const int tid = threadIdx.x;
    const int bh = blockIdx.y;
    const int m0 = blockIdx.x * 128;
    const int lane = tid & 31, warp = tid >> 5;
    const int wm = (warp & 3) * 32, wn = (warp >> 2) * 32;
    const int g = lane >> 2, t = lane & 3;
    const int lr = tid >> 2;
    const int lk = (tid & 3) * 4;

    const float* Ab = P + (size_t)bh * SSEQ * SSEQ + (size_t)(m0 + lr) * SSEQ + lk;
    const float* Bb = g_vT + (size_t)bh * 64 * SSEQ + (size_t)lr * SSEQ + lk;

    float4 ra0 = *(const float4*)(Ab);
    float4 ra1 = *(const float4*)(Ab + (size_t)64 * SSEQ);
    float4 rb0 = *(const float4*)(Bb);

    float c[2][4][4] = {};

    for (int k0 = 16; k0 <= SSEQ; k0 += 16) {
        *(uint4*)&As[lr][lk]      = cvt4(ra0);
        *(uint4*)&As[lr + 64][lk] = cvt4(ra1);
        *(uint4*)&Bs[lr][lk]      = cvt4(rb0);
        __syncthreads();
        if (k0 < SSEQ) {
            ra0 = *(const float4*)(Ab + k0);
            ra1 = *(const float4*)(Ab + (size_t)64 * SSEQ + k0);
            rb0 = *(const float4*)(Bb + k0);
        }
#pragma unroll
        for (int ks = 0; ks < 2; ks++) {
            const int kb = ks * 8;
            uint32_t af[2][4], bf[4][2];
#pragma unroll
            for (int mi = 0; mi < 2; mi++) {
                const int r = wm + mi * 16 + g;
                af[mi][0] = As[r][kb + t];
                af[mi][1] = As[r + 8][kb + t];
                af[mi][2] = As[r][kb + t + 4];
                af[mi][3] = As[r + 8][kb + t + 4];
            }
#pragma unroll
            for (int ni = 0; ni < 4; ni++) {
                const int cc = wn + ni * 8 + g;
                bf[ni][0] = Bs[cc][kb + t];
                bf[ni][1] = Bs[cc][kb + t + 4];
            }
#pragma unroll
            for (int mi = 0; mi < 2; mi++)
#pragma unroll
                for (int ni = 0; ni < 4; ni++)
                    mma_tf32(c[mi][ni], af[mi], bf[ni]);
        }
        __syncthreads();
    }

    const int b_ = bh >> 4, h = bh & 15;
#pragma unroll
    for (int mi = 0; mi < 2; mi++) {
#pragma unroll
        for (int rr = 0; rr < 2; rr++) {
            const int s = m0 + wm + mi * 16 + g + rr * 8;
#pragma unroll
            for (int ni = 0; ni < 4; ni++) {
                const int d = wn + ni * 8 + 2 * t;
                *(float2*)&g_attn[(size_t)(b_ * SSEQ + s) * DM + h * 64 + d] =
                    make_float2(c[mi][ni][rr * 2 + 0], c[mi][ni][rr * 2 + 1]);
            }
        }
    }
}

// ---------------------------------------------------------------------------
extern "C" void kernel_launch(void* const* d_in, const int* in_sizes, int n_in,
                              void* d_out, int out_size)
{
    const float* Q   = (const float*)d_in[0];
    const float* K   = (const float*)d_in[1];
    const float* V   = (const float*)d_in[2];
    const unsigned char* mask = (const unsigned char*)d_in[3];
    const float* WQw = (const float*)d_in[4];
    const float* WQb = (const float*)d_in[5];
    const float* WKw = (const float*)d_in[6];
    const float* WKb = (const float*)d_in[7];
    const float* WVw = (const float*)d_in[8];
    const float* WVb = (const float*)d_in[9];
    const float* Wow = (const float*)d_in[10];
    const float* Wob = (const float*)d_in[11];

    float* out   = (float*)d_out;                       // [B,S,D]
    float* attnw = out + (size_t)MTOT * DM;             // [B,H,S,S]

    float *pq, *pk, *pv, *pa;
    cudaGetSymbolAddress((void**)&pq, g_q);
    cudaGetSymbolAddress((void**)&pk, g_k);
    cudaGetSymbolAddress((void**)&pv, g_vT);
    cudaGetSymbolAddress((void**)&pa, g_attn);

    proj_tf32<<<dim3(8, 32), 256>>>(Q, WQw, WQb, pq, 1);
    proj_tf32<<<dim3(8, 32), 256>>>(K, WKw, WKb, pk, 1);
    proj_tf32<<<dim3(8, 32), 256>>>(V, WVw, WVb, pv, 2);

    scores_tf32<<<dim3(16, 16, 32), 256>>>(mask, attnw);
    softmax_kernel<<<BH * SSEQ, 256>>>(attnw);
    pv_tf32<<<dim3(16, 32), 256>>>(attnw);

    proj_tf32<<<dim3(8, 32), 256>>>(pa, Wow, Wob, out, 0);
}